// round 3
// baseline (speedup 1.0000x reference)
#include <cuda_runtime.h>
#include <cuda_bf16.h>

#define N_FEAT 1024
#define RANK 4
#define SCALING 0.25f
#define TPB 256   // 1024 floats / 4 per float4 = 256 threads

// out[row][j] = SCALING * sum_r ( (sum_i x[row][i]*A[r][i]) * B[j][r] )
__global__ __launch_bounds__(TPB) void lora_fused_kernel(
    const float* __restrict__ x,      // [M, 1024]
    const float* __restrict__ A,      // [4, 1024]
    const float* __restrict__ B,      // [1024, 4]
    float* __restrict__ out)          // [M, 1024]
{
    const int row = blockIdx.x;
    const int t   = threadIdx.x;
    const int lane = t & 31;
    const int warp = t >> 5;

    // ---- load one float4 of the row, dot against the 4 A rows ----
    const float4 xv = reinterpret_cast<const float4*>(x + (size_t)row * N_FEAT)[t];
    const float4 a0 = reinterpret_cast<const float4*>(A + 0 * N_FEAT)[t];
    const float4 a1 = reinterpret_cast<const float4*>(A + 1 * N_FEAT)[t];
    const float4 a2 = reinterpret_cast<const float4*>(A + 2 * N_FEAT)[t];
    const float4 a3 = reinterpret_cast<const float4*>(A + 3 * N_FEAT)[t];

    float p0 = xv.x * a0.x + xv.y * a0.y + xv.z * a0.z + xv.w * a0.w;
    float p1 = xv.x * a1.x + xv.y * a1.y + xv.z * a1.z + xv.w * a1.w;
    float p2 = xv.x * a2.x + xv.y * a2.y + xv.z * a2.z + xv.w * a2.w;
    float p3 = xv.x * a3.x + xv.y * a3.y + xv.z * a3.z + xv.w * a3.w;

    // ---- warp reduce all 4 partials ----
    #pragma unroll
    for (int off = 16; off > 0; off >>= 1) {
        p0 += __shfl_xor_sync(0xFFFFFFFFu, p0, off);
        p1 += __shfl_xor_sync(0xFFFFFFFFu, p1, off);
        p2 += __shfl_xor_sync(0xFFFFFFFFu, p2, off);
        p3 += __shfl_xor_sync(0xFFFFFFFFu, p3, off);
    }

    __shared__ float red[8][RANK];   // 8 warps
    __shared__ float h[RANK];
    if (lane == 0) {
        red[warp][0] = p0; red[warp][1] = p1;
        red[warp][2] = p2; red[warp][3] = p3;
    }
    __syncthreads();

    if (t < RANK) {
        float s = 0.f;
        #pragma unroll
        for (int w = 0; w < 8; ++w) s += red[w][t];
        h[t] = s * SCALING;
    }
    __syncthreads();

    const float h0 = h[0], h1 = h[1], h2 = h[2], h3 = h[3];

    // ---- expand: 4 contiguous output columns per thread ----
    const float4* Bv = reinterpret_cast<const float4*>(B);   // B row j = float4
    const float4 b0 = Bv[4 * t + 0];
    const float4 b1 = Bv[4 * t + 1];
    const float4 b2 = Bv[4 * t + 2];
    const float4 b3 = Bv[4 * t + 3];

    float4 o;
    o.x = h0 * b0.x + h1 * b0.y + h2 * b0.z + h3 * b0.w;
    o.y = h0 * b1.x + h1 * b1.y + h2 * b1.z + h3 * b1.w;
    o.z = h0 * b2.x + h1 * b2.y + h2 * b2.z + h3 * b2.w;
    o.w = h0 * b3.x + h1 * b3.y + h2 * b3.z + h3 * b3.w;

    reinterpret_cast<float4*>(out + (size_t)row * N_FEAT)[t] = o;
}

extern "C" void kernel_launch(void* const* d_in, const int* in_sizes, int n_in,
                              void* d_out, int out_size)
{
    const float* x = (const float*)d_in[0];
    const float* A = (const float*)d_in[1];
    const float* B = (const float*)d_in[2];
    float* out = (float*)d_out;

    const int rows = in_sizes[0] / N_FEAT;   // 4*8192 = 32768
    lora_fused_kernel<<<rows, TPB>>>(x, A, B, out);
}

// round 5
// speedup vs baseline: 2.1323x; 2.1323x over previous
#include <cuda_runtime.h>
#include <cuda_bf16.h>

#define N_FEAT 1024
#define RANK 4
#define SCALING 0.25f
#define TPB 256           // 1024 floats / 4 per float4
#define ROWS_PER_CTA 16
#define BATCH 4           // rows processed per register batch
#define NWARP 8

__global__ __launch_bounds__(TPB) void lora_fused_kernel(
    const float* __restrict__ x,      // [M, 1024]
    const float* __restrict__ A,      // [4, 1024]
    const float* __restrict__ B,      // [1024, 4]
    float* __restrict__ out)          // [M, 1024]
{
    const int t    = threadIdx.x;
    const int lane = t & 31;
    const int warp = t >> 5;
    const int row0 = blockIdx.x * ROWS_PER_CTA;

    // red[warp][row][rank], h[row][rank]
    __shared__ float4 red4[NWARP][ROWS_PER_CTA];   // float4 = 4 rank partials
    __shared__ float4 h4[ROWS_PER_CTA];

    // ---- A resident in registers for the whole CTA ----
    const float4 a0 = reinterpret_cast<const float4*>(A + 0 * N_FEAT)[t];
    const float4 a1 = reinterpret_cast<const float4*>(A + 1 * N_FEAT)[t];
    const float4 a2 = reinterpret_cast<const float4*>(A + 2 * N_FEAT)[t];
    const float4 a3 = reinterpret_cast<const float4*>(A + 3 * N_FEAT)[t];

    // ---- contraction phase: 4 batches of 4 rows ----
    #pragma unroll
    for (int b = 0; b < ROWS_PER_CTA / BATCH; ++b) {
        float4 xv[BATCH];
        #pragma unroll
        for (int i = 0; i < BATCH; ++i) {
            const int row = row0 + b * BATCH + i;
            xv[i] = reinterpret_cast<const float4*>(x + (size_t)row * N_FEAT)[t];
        }

        #pragma unroll
        for (int i = 0; i < BATCH; ++i) {
            float p0 = xv[i].x * a0.x + xv[i].y * a0.y + xv[i].z * a0.z + xv[i].w * a0.w;
            float p1 = xv[i].x * a1.x + xv[i].y * a1.y + xv[i].z * a1.z + xv[i].w * a1.w;
            float p2 = xv[i].x * a2.x + xv[i].y * a2.y + xv[i].z * a2.z + xv[i].w * a2.w;
            float p3 = xv[i].x * a3.x + xv[i].y * a3.y + xv[i].z * a3.z + xv[i].w * a3.w;

            #pragma unroll
            for (int off = 16; off > 0; off >>= 1) {
                p0 += __shfl_xor_sync(0xFFFFFFFFu, p0, off);
                p1 += __shfl_xor_sync(0xFFFFFFFFu, p1, off);
                p2 += __shfl_xor_sync(0xFFFFFFFFu, p2, off);
                p3 += __shfl_xor_sync(0xFFFFFFFFu, p3, off);
            }
            if (lane == 0)
                red4[warp][b * BATCH + i] = make_float4(p0, p1, p2, p3);
        }
    }
    __syncthreads();

    // ---- cross-warp finalize: 64 threads, one (row, rank) each ----
    if (t < ROWS_PER_CTA * RANK) {
        const int row  = t >> 2;
        const int rank = t & 3;
        const float* redf = reinterpret_cast<const float*>(red4);
        float s = 0.f;
        #pragma unroll
        for (int w = 0; w < NWARP; ++w)
            s += redf[(w * ROWS_PER_CTA + row) * RANK + rank];
        reinterpret_cast<float*>(h4)[t] = s * SCALING;
    }
    __syncthreads();

    // ---- expansion phase: B resident in registers, 16 rows of output ----
    const float4* Bv = reinterpret_cast<const float4*>(B);   // B row j = one float4
    const float4 b0 = Bv[4 * t + 0];
    const float4 b1 = Bv[4 * t + 1];
    const float4 b2 = Bv[4 * t + 2];
    const float4 b3 = Bv[4 * t + 3];

    #pragma unroll
    for (int r = 0; r < ROWS_PER_CTA; ++r) {
        const float4 h = h4[r];   // broadcast LDS.128
        float4 o;
        o.x = h.x * b0.x + h.y * b0.y + h.z * b0.z + h.w * b0.w;
        o.y = h.x * b1.x + h.y * b1.y + h.z * b1.z + h.w * b1.w;
        o.z = h.x * b2.x + h.y * b2.y + h.z * b2.z + h.w * b2.w;
        o.w = h.x * b3.x + h.y * b3.y + h.z * b3.z + h.w * b3.w;
        reinterpret_cast<float4*>(out + (size_t)(row0 + r) * N_FEAT)[t] = o;
    }
}

extern "C" void kernel_launch(void* const* d_in, const int* in_sizes, int n_in,
                              void* d_out, int out_size)
{
    const float* x = (const float*)d_in[0];
    const float* A = (const float*)d_in[1];
    const float* B = (const float*)d_in[2];
    float* out = (float*)d_out;

    const int rows = in_sizes[0] / N_FEAT;   // 32768
    lora_fused_kernel<<<rows / ROWS_PER_CTA, TPB>>>(x, A, B, out);
}